// round 2
// baseline (speedup 1.0000x reference)
#include <cuda_runtime.h>
#include <math.h>
#include <stdint.h>

#define H 2048
#define E 64
#define S 4096
#define B 2
#define SW 1024
#define NEGF (-3.4028234663852886e38f)   // -FLT_MAX == finfo(float32).min

#define OFF_SLID 33554432ull             // 2*4096*4096
#define OFF_W    67108864ull
#define OFF_I    67141632ull             // OFF_W + 8192*4

// scratch (no allocations allowed)
__device__ float g_w2[E * H];            // proj_w * scale * H^-0.5
__device__ int   g_gid[B * S];           // vision group ids

// ---------------------------------------------------------------------------
// K0: fold scale and H^-0.5 into proj_w
// ---------------------------------------------------------------------------
__global__ void fold_w_kernel(const float* __restrict__ pw,
                              const float* __restrict__ scale) {
    int i = blockIdx.x * 256 + threadIdx.x;     // grid 512*256 = 131072 = E*H
    g_w2[i] = pw[i] * scale[i & (H - 1)] * 0.022097086912079608f; // 1/sqrt(2048)
}

// ---------------------------------------------------------------------------
// K1: vision group ids via block prefix scan (1 block per batch)
// ---------------------------------------------------------------------------
__global__ void gid_scan_kernel(const int* __restrict__ mm) {
    __shared__ int ss[1024];
    int b = blockIdx.x, t = threadIdx.x;
    const int* m = mm + b * S;
    int base = t * 4;
    int prev = (base > 0) ? m[base - 1] : 0;
    int m0 = m[base], m1 = m[base + 1], m2 = m[base + 2], m3 = m[base + 3];
    bool pv = (prev == 1) | (prev == 2);
    bool v0 = (m0 == 1) | (m0 == 2);
    bool v1 = (m1 == 1) | (m1 == 2);
    bool v2 = (m2 == 1) | (m2 == 2);
    bool v3 = (m3 == 1) | (m3 == 2);
    int s0 = (v0 && !pv), s1 = (v1 && !v0), s2 = (v2 && !v1), s3 = (v3 && !v2);
    int c = s0 + s1 + s2 + s3;
    ss[t] = c;
    __syncthreads();
    for (int off = 1; off < 1024; off <<= 1) {
        int v = (t >= off) ? ss[t - off] : 0;
        __syncthreads();
        ss[t] += v;
        __syncthreads();
    }
    int run = ss[t] - c;   // exclusive prefix of starts
    int* g = g_gid + b * S + base;
    run += s0; g[0] = v0 ? run - 1 : -1;
    run += s1; g[1] = v1 ? run - 1 : -1;
    run += s2; g[2] = v2 ? run - 1 : -1;
    run += s3; g[3] = v3 ? run - 1 : -1;
}

// ---------------------------------------------------------------------------
// K2: mask kernel. One block handles 8 q-rows of one batch.
// Writes full_mask and sliding_mask rows with float4 stores (write-bound).
// ---------------------------------------------------------------------------
__global__ __launch_bounds__(256) void mask_kernel(const int* __restrict__ packed,
                                                   float* __restrict__ out) {
    __shared__ __align__(16) int spk[S];
    __shared__ __align__(16) int sgd[S];
    int b = blockIdx.y;
    int tid = threadIdx.x;
    const int* pk = packed + b * S;
    const int* gd = g_gid + b * S;
    for (int i = tid; i < S; i += 256) { spk[i] = pk[i]; sgd[i] = gd[i]; }
    __syncthreads();

    float* fullb = out + (size_t)b * S * S;
    float* slidb = out + OFF_SLID + (size_t)b * S * S;

    for (int qi = 0; qi < 8; qi++) {
        int q = blockIdx.x * 8 + qi;
        int pq = spk[q];
        int gq = sgd[q];
        bool pq_ok = pq > 0;
        float4* fo = (float4*)(fullb + (size_t)q * S);
        float4* so = (float4*)(slidb + (size_t)q * S);
        #pragma unroll
        for (int it = 0; it < 4; it++) {
            int k4 = tid + it * 256;
            int kv = k4 * 4;
            int4 p4 = ((const int4*)spk)[k4];
            int4 g4 = ((const int4*)sgd)[k4];
            float4 f, sl;
            {
                bool same = pq_ok & (p4.x == pq);
                bool caus = q >= (kv + 0);
                f.x  = (same & caus) ? 0.0f : NEGF;
                bool s2 = same & ((caus & ((q - (kv + 0)) < SW)) | ((gq >= 0) & (g4.x == gq)));
                sl.x = s2 ? 0.0f : NEGF;
            }
            {
                bool same = pq_ok & (p4.y == pq);
                bool caus = q >= (kv + 1);
                f.y  = (same & caus) ? 0.0f : NEGF;
                bool s2 = same & ((caus & ((q - (kv + 1)) < SW)) | ((gq >= 0) & (g4.y == gq)));
                sl.y = s2 ? 0.0f : NEGF;
            }
            {
                bool same = pq_ok & (p4.z == pq);
                bool caus = q >= (kv + 2);
                f.z  = (same & caus) ? 0.0f : NEGF;
                bool s2 = same & ((caus & ((q - (kv + 2)) < SW)) | ((gq >= 0) & (g4.z == gq)));
                sl.z = s2 ? 0.0f : NEGF;
            }
            {
                bool same = pq_ok & (p4.w == pq);
                bool caus = q >= (kv + 3);
                f.w  = (same & caus) ? 0.0f : NEGF;
                bool s2 = same & ((caus & ((q - (kv + 3)) < SW)) | ((gq >= 0) & (g4.w == gq)));
                sl.w = s2 ? 0.0f : NEGF;
            }
            fo[k4] = f;
            so[k4] = sl;
        }
    }
}

// ---------------------------------------------------------------------------
// K3: gate. One block = 64 rows x 64 experts fp32 GEMM tile (K=2048),
// fused rmsnorm factor + top-4 + renormalized softmax.
// ---------------------------------------------------------------------------
__global__ __launch_bounds__(256) void gate_kernel(const float* __restrict__ x,
                                                   float* __restrict__ out) {
    __shared__ float Xs[32][68];     // k-major, padded
    __shared__ float Ws[32][68];
    __shared__ float s_r[64];
    __shared__ float s_l[64][68];

    int bm  = blockIdx.x;                 // 128 blocks of 64 rows
    int tid = threadIdx.x;
    int w   = tid >> 5, lane = tid & 31;
    const float* xb = x + (size_t)bm * 64 * H;

    // Phase A: rms factor per row (warp w handles rows w, w+8, ...)
    for (int rr = w; rr < 64; rr += 8) {
        const float4* xr = (const float4*)(xb + (size_t)rr * H);
        float s = 0.0f;
        #pragma unroll
        for (int i = 0; i < 16; i++) {
            float4 v = xr[lane + i * 32];
            s += v.x * v.x + v.y * v.y + v.z * v.z + v.w * v.w;
        }
        #pragma unroll
        for (int o = 16; o; o >>= 1) s += __shfl_xor_sync(0xffffffffu, s, o);
        if (lane == 0) s_r[rr] = rsqrtf(s * (1.0f / H) + 1e-6f);
    }

    // Phase B: GEMM, each thread owns 4 rows x 4 experts
    float acc[4][4] = {};
    int tr = tid >> 4, tc = tid & 15;
    for (int kt = 0; kt < 64; kt++) {
        __syncthreads();
        #pragma unroll
        for (int i = 0; i < 8; i++) {
            int idx = tid + i * 256;
            int row = idx >> 5;
            int k   = idx & 31;
            Xs[k][row] = xb[(size_t)row * H + kt * 32 + k];
            Ws[k][row] = g_w2[row * H + kt * 32 + k];   // row == expert here
        }
        __syncthreads();
        #pragma unroll
        for (int k = 0; k < 32; k++) {
            float4 xv = *(const float4*)&Xs[k][tr * 4];
            float4 wv = *(const float4*)&Ws[k][tc * 4];
            float xa[4] = { xv.x, xv.y, xv.z, xv.w };
            float wa[4] = { wv.x, wv.y, wv.z, wv.w };
            #pragma unroll
            for (int i = 0; i < 4; i++)
                #pragma unroll
                for (int j = 0; j < 4; j++)
                    acc[i][j] = fmaf(xa[i], wa[j], acc[i][j]);
        }
    }

    __syncthreads();
    #pragma unroll
    for (int i = 0; i < 4; i++)
        #pragma unroll
        for (int j = 0; j < 4; j++)
            s_l[tr * 4 + i][tc * 4 + j] = acc[i][j];
    __syncthreads();

    // Phase C: per-row top-4 + softmax over top-4 (== renormalized topk probs)
    for (int rr = w; rr < 64; rr += 8) {
        float r = s_r[rr];
        float v0 = r * s_l[rr][lane];
        float v1 = r * s_l[rr][lane + 32];
        float vals[4]; int ids[4];
        #pragma unroll
        for (int t4 = 0; t4 < 4; t4++) {
            float cv; int ci;
            if (v1 > v0) { cv = v1; ci = lane + 32; }
            else         { cv = v0; ci = lane; }       // tie -> smaller index
            #pragma unroll
            for (int o = 16; o; o >>= 1) {
                float ov = __shfl_xor_sync(0xffffffffu, cv, o);
                int   oi = __shfl_xor_sync(0xffffffffu, ci, o);
                if (ov > cv || (ov == cv && oi < ci)) { cv = ov; ci = oi; }
            }
            vals[t4] = cv; ids[t4] = ci;
            if (ci < 32) { if (lane == ci)      v0 = -3.4e38f; }
            else         { if (lane == ci - 32) v1 = -3.4e38f; }
        }
        if (lane == 0) {
            int row = bm * 64 + rr;
            float m = vals[0];
            float e0 = expf(vals[0] - m), e1 = expf(vals[1] - m);
            float e2 = expf(vals[2] - m), e3 = expf(vals[3] - m);
            float inv = 1.0f / (e0 + e1 + e2 + e3);
            float* ow = out + OFF_W + (size_t)row * 4;
            float* oi = out + OFF_I + (size_t)row * 4;
            ow[0] = e0 * inv; ow[1] = e1 * inv; ow[2] = e2 * inv; ow[3] = e3 * inv;
            oi[0] = (float)ids[0]; oi[1] = (float)ids[1];
            oi[2] = (float)ids[2]; oi[3] = (float)ids[3];
        }
    }
}

// ---------------------------------------------------------------------------
extern "C" void kernel_launch(void* const* d_in, const int* in_sizes, int n_in,
                              void* d_out, int out_size) {
    const float* x      = (const float*)d_in[0];
    const int*   packed = (const int*)d_in[1];
    const int*   mm     = (const int*)d_in[2];
    const float* scale  = (const float*)d_in[3];
    const float* pw     = (const float*)d_in[4];
    float* out = (float*)d_out;

    fold_w_kernel<<<512, 256>>>(pw, scale);
    gid_scan_kernel<<<B, 1024>>>(mm);
    gate_kernel<<<128, 256>>>(x, out);
    mask_kernel<<<dim3(S / 8, B), 256>>>(packed, out);
}